// round 1
// baseline (speedup 1.0000x reference)
#include <cuda_runtime.h>
#include <math.h>

#define BB 4
#define LL 8192
#define HH 64
#define NSTATE 16
#define DBLK 4
#define DCONV 16
#define DINNER 128
#define HEADDIM 16
#define NHEADS 8
#define CONV_DIM 160
#define DPROJ 296
#define CHUNK 128
#define NCHUNK 64
#define NTOK (BB*LL)

// ---------------- scratch (device globals; no allocation) ----------------
__device__ float g_h[NTOK*HH];                                   // residual stream
__device__ float g_zx[NTOK*DPROJ];                               // in_proj output
__device__ float g_xBC[NTOK*CONV_DIM];                           // post-conv silu
__device__ float g_acs[BB*NCHUNK*NHEADS*CHUNK];                  // within-chunk cumsum of dA
__device__ float g_stl[BB*NCHUNK*NHEADS*HEADDIM*NSTATE];         // local chunk states
__device__ float g_prev[BB*NCHUNK*NHEADS*HEADDIM*NSTATE];        // scanned prev states
__device__ float g_y[NTOK*DINNER];                               // Y_diag + skip

// ---------------- embed: h = x * w_in ----------------
__global__ void k_embed(const float* __restrict__ x, const float* __restrict__ w_in){
    int i = blockIdx.x*blockDim.x + threadIdx.x;   // NTOK*HH
    int tok = i >> 6; int d = i & 63;
    g_h[i] = x[tok] * w_in[d];
}

// ---------------- in_proj: zx[t,e] = sum_d h[t,d] * w[e,d] ----------------
// block: 32 tokens, 320 threads (thread = one output channel e).
__global__ void __launch_bounds__(320) k_inproj(const float* __restrict__ w){
    __shared__ float hs[32*64];
    int tid = threadIdx.x;
    int t0 = blockIdx.x*32;
    for (int i=tid; i<32*64; i+=320) hs[i] = g_h[t0*64 + i];
    __syncthreads();
    if (tid >= DPROJ) return;
    float wr[64];
    #pragma unroll
    for (int d=0; d<64; d++) wr[d] = w[tid*64 + d];
    float acc[32];
    #pragma unroll
    for (int t=0; t<32; t++) acc[t] = 0.f;
    #pragma unroll
    for (int d=0; d<64; d+=4){
        #pragma unroll
        for (int t=0; t<32; t++){
            float4 h4 = *(const float4*)&hs[t*64 + d];
            acc[t] = fmaf(wr[d],   h4.x, acc[t]);
            acc[t] = fmaf(wr[d+1], h4.y, acc[t]);
            acc[t] = fmaf(wr[d+2], h4.z, acc[t]);
            acc[t] = fmaf(wr[d+3], h4.w, acc[t]);
        }
    }
    #pragma unroll
    for (int t=0; t<32; t++) g_zx[(t0+t)*DPROJ + tid] = acc[t];
}

// ---------------- depthwise causal conv + bias + silu ----------------
__global__ void k_conv(const float* __restrict__ cw, const float* __restrict__ cb){
    int idx = blockIdx.x*blockDim.x + threadIdx.x;    // NTOK*CONV_DIM
    int ch  = idx % CONV_DIM;
    int tok = idx / CONV_DIM;
    int b = tok / LL, l = tok % LL;
    float acc = cb[ch];
    #pragma unroll
    for (int k=0; k<DCONV; k++){
        int ls = l - (DCONV-1) + k;
        if (ls >= 0)
            acc = fmaf(cw[ch*DCONV + k], g_zx[(b*LL + ls)*DPROJ + DINNER + ch], acc);
    }
    g_xBC[idx] = acc / (1.f + __expf(-acc));
}

// ---------------- intra-chunk: cumsum, Y_diag(+skip), local states ----------------
__global__ void __launch_bounds__(256) k_intra(const float* __restrict__ dtb,
                                               const float* __restrict__ alog,
                                               const float* __restrict__ dskip){
    int bc = blockIdx.x; int b = bc / NCHUNK; int c = bc % NCHUNK;
    int tid = threadIdx.x;
    __shared__ float Bs[CHUNK*16];
    __shared__ float Cs[CHUNK*16];
    __shared__ float Xs[CHUNK*16];   // raw xh (dt folded into coefficients)
    __shared__ float dts[CHUNK];
    __shared__ float acs[CHUNK];
    __shared__ float dec[CHUNK];     // exp(Atot - acs)*dt  (for local states)
    int tokbase = b*LL + c*CHUNK;

    for (int i=tid; i<CHUNK*16; i+=256){
        int l = i>>4, n = i&15;
        Bs[i] = g_xBC[(tokbase+l)*CONV_DIM + DINNER + n];
        Cs[i] = g_xBC[(tokbase+l)*CONV_DIM + DINNER + NSTATE + n];
    }
    __syncthreads();

    for (int h=0; h<NHEADS; h++){
        // dt = softplus(raw + dtb), dA = dt * (-exp(A_log))
        if (tid < CHUNK){
            float v = g_zx[(tokbase+tid)*DPROJ + DINNER + CONV_DIM + h] + dtb[h];
            float dt = (v > 20.f) ? v : log1pf(__expf(v));
            dts[tid] = dt;
            acs[tid] = dt * (-__expf(alog[h]));
        }
        __syncthreads();
        // inclusive scan (Hillis-Steele) of dA -> acs
        for (int off=1; off<CHUNK; off<<=1){
            float v = 0.f;
            if (tid < CHUNK && tid >= off) v = acs[tid-off];
            __syncthreads();
            if (tid < CHUNK) acs[tid] += v;
            __syncthreads();
        }
        // load raw xh for this head; compute decay*dt
        for (int i=tid; i<CHUNK*16; i+=256){
            int l = i>>4, p = i&15;
            Xs[i] = g_xBC[(tokbase+l)*CONV_DIM + h*HEADDIM + p];
        }
        if (tid < CHUNK){
            float at = acs[CHUNK-1];
            dec[tid] = __expf(at - acs[tid]) * dts[tid];
        }
        __syncthreads();

        // local chunk state: thread = (p,n)
        {
            int p = tid>>4, n = tid&15;
            float s = 0.f;
            for (int l=0; l<CHUNK; l++)
                s = fmaf(Bs[l*16+n]*dec[l], Xs[l*16+p], s);
            g_stl[((bc*NHEADS + h)*HEADDIM + p)*NSTATE + n] = s;
        }
        if (tid < CHUNK) g_acs[(bc*NHEADS + h)*CHUNK + tid] = acs[tid];

        // Y_diag (+ skip): thread = (l, p-half of 8)
        {
            int l = tid>>1; int p0 = (tid&1)*8;
            float4 c0 = *(const float4*)&Cs[l*16+0];
            float4 c1 = *(const float4*)&Cs[l*16+4];
            float4 c2 = *(const float4*)&Cs[l*16+8];
            float4 c3 = *(const float4*)&Cs[l*16+12];
            float al = acs[l];
            float dsk = dskip[h];
            float4 y0 = *(const float4*)&Xs[l*16+p0];
            float4 y1 = *(const float4*)&Xs[l*16+p0+4];
            y0.x*=dsk; y0.y*=dsk; y0.z*=dsk; y0.w*=dsk;
            y1.x*=dsk; y1.y*=dsk; y1.z*=dsk; y1.w*=dsk;
            for (int s=0; s<=l; s++){
                float4 b0 = *(const float4*)&Bs[s*16+0];
                float4 b1 = *(const float4*)&Bs[s*16+4];
                float4 b2 = *(const float4*)&Bs[s*16+8];
                float4 b3 = *(const float4*)&Bs[s*16+12];
                float dot = c0.x*b0.x + c0.y*b0.y + c0.z*b0.z + c0.w*b0.w
                          + c1.x*b1.x + c1.y*b1.y + c1.z*b1.z + c1.w*b1.w
                          + c2.x*b2.x + c2.y*b2.y + c2.z*b2.z + c2.w*b2.w
                          + c3.x*b3.x + c3.y*b3.y + c3.z*b3.z + c3.w*b3.w;
                float wgt = dot * __expf(al - acs[s]) * dts[s];
                float4 x0 = *(const float4*)&Xs[s*16+p0];
                float4 x1 = *(const float4*)&Xs[s*16+p0+4];
                y0.x = fmaf(wgt, x0.x, y0.x); y0.y = fmaf(wgt, x0.y, y0.y);
                y0.z = fmaf(wgt, x0.z, y0.z); y0.w = fmaf(wgt, x0.w, y0.w);
                y1.x = fmaf(wgt, x1.x, y1.x); y1.y = fmaf(wgt, x1.y, y1.y);
                y1.z = fmaf(wgt, x1.z, y1.z); y1.w = fmaf(wgt, x1.w, y1.w);
            }
            float* yo = &g_y[(tokbase+l)*DINNER + h*HEADDIM + p0];
            *(float4*)&yo[0] = y0;
            *(float4*)&yo[4] = y1;
        }
        __syncthreads();
    }
}

// ---------------- inter-chunk scan over 64 chunks ----------------
__global__ void k_scan(const float* __restrict__ ist){
    int b = blockIdx.x>>3, h = blockIdx.x&7;
    int tid = threadIdx.x;                 // (p,n) = tid
    __shared__ float ats[NCHUNK];
    if (tid < NCHUNK)
        ats[tid] = __expf(g_acs[((b*NCHUNK + tid)*NHEADS + h)*CHUNK + CHUNK-1]);
    __syncthreads();
    float S = ist[(h*HEADDIM + (tid>>4))*NSTATE + (tid&15)];
    int idx0 = ((b*NCHUNK)*NHEADS + h)*256 + tid;
    for (int c0=0; c0<NCHUNK; c0+=8){
        float buf[8];
        #pragma unroll
        for (int j=0; j<8; j++) buf[j] = g_stl[idx0 + (c0+j)*(NHEADS*256)];
        #pragma unroll
        for (int j=0; j<8; j++){
            g_prev[idx0 + (c0+j)*(NHEADS*256)] = S;
            S = fmaf(S, ats[c0+j], buf[j]);
        }
    }
}

// ---------------- Y_off + gate + RMSnorm + out_proj + softsign + MLP + residual ----------------
#define SMEM_OUT_FLOATS (128*64 + 64*64 + 128 + 64 + 8*128 + 8*64 + 8*16 + 8*8)
__global__ void __launch_bounds__(256) k_out(const float* __restrict__ nw,
                                             const float* __restrict__ ow,
                                             const float* __restrict__ mw,
                                             const float* __restrict__ mb){
    extern __shared__ float sm[];
    float* ow_t = sm;                 // [e*64 + d] transposed out_proj
    float* mw_t = ow_t + 128*64;      // [e*64 + d] transposed mlp
    float* nws  = mw_t + 64*64;       // 128
    float* mbs  = nws + 128;          // 64
    float* yrow = mbs + 64;           // [8][128]
    float* trow = yrow + 8*128;       // [8][64]
    float* cmr  = trow + 8*64;        // [8][16]
    float* ear  = cmr + 8*16;         // [8][8]
    int tid = threadIdx.x, w = tid>>5, lane = tid&31;

    for (int i=tid; i<128*64; i+=256){ int e=i>>6, d=i&63; ow_t[i] = ow[d*128 + e]; }
    for (int i=tid; i<64*64;  i+=256){ int e=i>>6, d=i&63; mw_t[i] = mw[d*64 + e]; }
    if (tid < 128) nws[tid] = nw[tid];
    if (tid < 64)  mbs[tid] = mb[tid];
    __syncthreads();

    int tok = blockIdx.x*8 + w;
    int b = tok >> 13, l = tok & (LL-1);
    int c = l >> 7, lin = l & (CHUNK-1);
    int bc = b*NCHUNK + c;

    if (lane < 16) cmr[w*16+lane] = g_xBC[tok*CONV_DIM + DINNER + NSTATE + lane];
    if (lane < 8)  ear[w*8+lane]  = __expf(g_acs[(bc*NHEADS + lane)*CHUNK + lin]);
    __syncwarp();

    float yv[4]; float ss = 0.f;
    #pragma unroll
    for (int j=0; j<4; j++){
        int ch = lane + 32*j; int h = ch>>4, p = ch&15;
        const float* pv = &g_prev[((bc*NHEADS + h)*HEADDIM + p)*NSTATE];
        float off = 0.f;
        #pragma unroll
        for (int n=0; n<16; n++) off = fmaf(cmr[w*16+n], pv[n], off);
        float y = g_y[tok*DINNER + ch] + ear[w*8+h]*off;
        float z = g_zx[tok*DPROJ + ch];
        y *= z / (1.f + __expf(-z));
        yv[j] = y; ss = fmaf(y, y, ss);
    }
    #pragma unroll
    for (int o=16; o; o>>=1) ss += __shfl_xor_sync(~0u, ss, o);
    float scale = rsqrtf(ss*(1.f/128.f) + 1e-5f);
    #pragma unroll
    for (int j=0; j<4; j++){ int ch = lane + 32*j; yrow[w*128+ch] = yv[j]*scale*nws[ch]; }
    __syncwarp();

    float o1 = 0.f, o2 = 0.f;
    #pragma unroll 8
    for (int e=0; e<128; e++){
        float y2 = yrow[w*128+e];
        o1 = fmaf(y2, ow_t[e*64 + lane],      o1);
        o2 = fmaf(y2, ow_t[e*64 + lane + 32], o2);
    }
    o1 = o1 * rsqrtf(1.f + o1*o1);
    o2 = o2 * rsqrtf(1.f + o2*o2);
    trow[w*64 + lane] = o1; trow[w*64 + lane + 32] = o2;
    __syncwarp();

    float m1 = mbs[lane], m2 = mbs[lane+32];
    #pragma unroll 8
    for (int e=0; e<64; e++){
        float tv = trow[w*64+e];
        m1 = fmaf(tv, mw_t[e*64 + lane],      m1);
        m2 = fmaf(tv, mw_t[e*64 + lane + 32], m2);
    }
    g_h[tok*HH + lane]      += m1;
    g_h[tok*HH + lane + 32] += m2;
}

// ---------------- final: out = h . w_out ----------------
__global__ void k_final(const float* __restrict__ wo, float* __restrict__ out){
    int tid = threadIdx.x;
    int tok = blockIdx.x*8 + (tid>>5); int lane = tid&31;
    float v = g_h[tok*HH + lane]*wo[lane] + g_h[tok*HH + lane + 32]*wo[lane+32];
    #pragma unroll
    for (int o=16; o; o>>=1) v += __shfl_xor_sync(~0u, v, o);
    if (lane == 0) out[tok] = v;
}

extern "C" void kernel_launch(void* const* d_in, const int* in_sizes, int n_in,
                              void* d_out, int out_size){
    const float* x    = (const float*)d_in[0];
    const float* w_in = (const float*)d_in[1];
    const float* w_out= (const float*)d_in[2];
    const float* ipw  = (const float*)d_in[3];
    const float* cw   = (const float*)d_in[4];
    const float* cb   = (const float*)d_in[5];
    const float* dtb  = (const float*)d_in[6];
    const float* alog = (const float*)d_in[7];
    const float* dsk  = (const float*)d_in[8];
    const float* ist  = (const float*)d_in[9];
    const float* nw   = (const float*)d_in[10];
    const float* opw  = (const float*)d_in[11];
    const float* mw   = (const float*)d_in[12];
    const float* mb   = (const float*)d_in[13];
    float* out = (float*)d_out;

    cudaFuncSetAttribute(k_out, cudaFuncAttributeMaxDynamicSharedMemorySize,
                         SMEM_OUT_FLOATS*4);

    k_embed<<<NTOK*HH/256, 256>>>(x, w_in);
    for (int i=0; i<DBLK; i++){
        k_inproj<<<NTOK/32, 320>>>(ipw + (size_t)i*DPROJ*HH);
        k_conv<<<NTOK*CONV_DIM/256, 256>>>(cw + i*CONV_DIM*DCONV, cb + i*CONV_DIM);
        k_intra<<<BB*NCHUNK, 256>>>(dtb + i*NHEADS, alog + i*NHEADS, dsk + i*NHEADS);
        k_scan<<<BB*NHEADS, 256>>>(ist + (size_t)i*NHEADS*HEADDIM*NSTATE);
        k_out<<<NTOK/8, 256, SMEM_OUT_FLOATS*4>>>(nw + i*DINNER,
                                                  opw + (size_t)i*HH*DINNER,
                                                  mw + i*HH*HH, mb + i*HH);
    }
    k_final<<<NTOK/8, 256>>>(w_out, out);
}

// round 2
// speedup vs baseline: 1.4297x; 1.4297x over previous
#include <cuda_runtime.h>
#include <math.h>

#define BB 4
#define LL 8192
#define HH 64
#define NSTATE 16
#define DBLK 4
#define DCONV 16
#define DINNER 128
#define HEADDIM 16
#define NHEADS 8
#define CONV_DIM 160
#define DPROJ 296
#define CHUNK 128
#define NCHUNK 64
#define NTOK (BB*LL)

// ---------------- scratch (device globals; no allocation) ----------------
__device__ float g_h[NTOK*HH];                                   // residual stream
__device__ float g_zx[NTOK*DPROJ];                               // in_proj output
__device__ float g_xBC[NTOK*CONV_DIM];                           // post-conv silu
__device__ float g_acs[BB*NCHUNK*NHEADS*CHUNK];                  // within-chunk cumsum of dA
__device__ float g_stl[BB*NCHUNK*NHEADS*HEADDIM*NSTATE];         // local chunk states
__device__ float g_prev[BB*NCHUNK*NHEADS*HEADDIM*NSTATE];        // scanned prev states
__device__ float g_y[NTOK*DINNER];                               // Y_diag + skip

// ---------------- embed: h = x * w_in ----------------
__global__ void k_embed(const float* __restrict__ x, const float* __restrict__ w_in){
    int i = blockIdx.x*blockDim.x + threadIdx.x;   // NTOK*HH
    int tok = i >> 6; int d = i & 63;
    g_h[i] = x[tok] * w_in[d];
}

// ---------------- in_proj: zx[t,e] = sum_d h[t,d] * w[e,d] ----------------
// block: 16 tokens, 320 threads (thread = one output channel e).
__global__ void __launch_bounds__(320) k_inproj(const float* __restrict__ w){
    __shared__ float hs[16*64];
    int tid = threadIdx.x;
    int t0 = blockIdx.x*16;
    for (int i=tid; i<16*64; i+=320) hs[i] = g_h[t0*64 + i];
    __syncthreads();
    if (tid >= DPROJ) return;
    float wr[64];
    #pragma unroll
    for (int d=0; d<64; d++) wr[d] = w[tid*64 + d];
    float acc[16];
    #pragma unroll
    for (int t=0; t<16; t++) acc[t] = 0.f;
    #pragma unroll
    for (int d=0; d<64; d+=4){
        #pragma unroll
        for (int t=0; t<16; t++){
            float4 h4 = *(const float4*)&hs[t*64 + d];
            acc[t] = fmaf(wr[d],   h4.x, acc[t]);
            acc[t] = fmaf(wr[d+1], h4.y, acc[t]);
            acc[t] = fmaf(wr[d+2], h4.z, acc[t]);
            acc[t] = fmaf(wr[d+3], h4.w, acc[t]);
        }
    }
    #pragma unroll
    for (int t=0; t<16; t++) g_zx[(t0+t)*DPROJ + tid] = acc[t];
}

// ---------------- depthwise causal conv + bias + silu (4 tokens/thread) ----------------
__global__ void __launch_bounds__(256) k_conv(const float* __restrict__ cw, const float* __restrict__ cb){
    int idx = blockIdx.x*blockDim.x + threadIdx.x;    // (NTOK/4)*CONV_DIM
    int ch  = idx % CONV_DIM;
    int grp = idx / CONV_DIM;
    int tok0 = grp*4;
    int b = tok0 / LL, l0 = tok0 % LL;
    float wv[DCONV];
    #pragma unroll
    for (int k=0; k<DCONV; k++) wv[k] = cw[ch*DCONV + k];
    float in[DCONV+3];
    #pragma unroll
    for (int k=0; k<DCONV+3; k++){
        int ls = l0 - (DCONV-1) + k;
        in[k] = (ls >= 0) ? g_zx[(b*LL + ls)*DPROJ + DINNER + ch] : 0.f;
    }
    float bias = cb[ch];
    #pragma unroll
    for (int j=0; j<4; j++){
        float acc = bias;
        #pragma unroll
        for (int k=0; k<DCONV; k++) acc = fmaf(wv[k], in[j+k], acc);
        g_xBC[(tok0+j)*CONV_DIM + ch] = acc / (1.f + __expf(-acc));
    }
}

// ---------------- intra-chunk: one block per (b,c,head) ----------------
__global__ void __launch_bounds__(256) k_intra(const float* __restrict__ dtb,
                                               const float* __restrict__ alog,
                                               const float* __restrict__ dskip){
    int blk = blockIdx.x;
    int h  = blk & (NHEADS-1);
    int bc = blk >> 3;
    int b = bc / NCHUNK, c = bc % NCHUNK;
    int tid = threadIdx.x, lane = tid & 31;
    __shared__ float Bs[CHUNK*16];   // B * dt  (dt folded)
    __shared__ float Cs[CHUNK*16];
    __shared__ float Xs[CHUNK*16];   // raw xh
    __shared__ float dts[CHUNK];
    __shared__ float acs[CHUNK];
    __shared__ float dec[CHUNK];     // exp(Atot - acs)
    __shared__ float wsum[4];
    int tokbase = b*LL + c*CHUNK;

    // dt = softplus(raw + dtb), dA = dt*(-exp(A_log)); shuffle inclusive scan
    if (tid < CHUNK){
        float v = g_zx[(tokbase+tid)*DPROJ + DINNER + CONV_DIM + h] + dtb[h];
        float dt = (v > 20.f) ? v : log1pf(__expf(v));
        dts[tid] = dt;
        float s = dt * (-__expf(alog[h]));
        #pragma unroll
        for (int off=1; off<32; off<<=1){
            float u = __shfl_up_sync(0xffffffffu, s, off);
            if (lane >= off) s += u;
        }
        acs[tid] = s;
        if (lane == 31) wsum[tid>>5] = s;
    }
    __syncthreads();
    if (tid < CHUNK){
        int wi = tid>>5; float o = 0.f;
        for (int j=0; j<wi; j++) o += wsum[j];
        acs[tid] += o;
    }
    __syncthreads();

    // load tiles (B folded with dt), dec, store cumsum
    for (int i=tid; i<CHUNK*16; i+=256){
        int l = i>>4, n = i&15;
        const float* row = &g_xBC[(tokbase+l)*CONV_DIM];
        Bs[i] = row[DINNER + n] * dts[l];
        Cs[i] = row[DINNER + NSTATE + n];
        Xs[i] = row[h*HEADDIM + n];
    }
    if (tid < CHUNK){
        dec[tid] = __expf(acs[CHUNK-1] - acs[tid]);
        g_acs[(bc*NHEADS + h)*CHUNK + tid] = acs[tid];
    }
    __syncthreads();

    // local chunk state: thread = (p,n)
    {
        int p = tid>>4, n = tid&15;
        float s = 0.f;
        for (int l=0; l<CHUNK; l++)
            s = fmaf(Bs[l*16+n]*dec[l], Xs[l*16+p], s);
        g_stl[((bc*NHEADS + h)*HEADDIM + p)*NSTATE + n] = s;
    }

    // Y_diag (+ skip): thread = (l, p-half of 8)
    {
        int l = tid>>1; int p0 = (tid&1)*8;
        float4 c0 = *(const float4*)&Cs[l*16+0];
        float4 c1 = *(const float4*)&Cs[l*16+4];
        float4 c2 = *(const float4*)&Cs[l*16+8];
        float4 c3 = *(const float4*)&Cs[l*16+12];
        float al = acs[l];
        float dsk = dskip[h];
        float4 y0 = *(const float4*)&Xs[l*16+p0];
        float4 y1 = *(const float4*)&Xs[l*16+p0+4];
        y0.x*=dsk; y0.y*=dsk; y0.z*=dsk; y0.w*=dsk;
        y1.x*=dsk; y1.y*=dsk; y1.z*=dsk; y1.w*=dsk;
        for (int s=0; s<=l; s++){
            float4 b0 = *(const float4*)&Bs[s*16+0];
            float4 b1 = *(const float4*)&Bs[s*16+4];
            float4 b2 = *(const float4*)&Bs[s*16+8];
            float4 b3 = *(const float4*)&Bs[s*16+12];
            float dot = c0.x*b0.x + c0.y*b0.y + c0.z*b0.z + c0.w*b0.w
                      + c1.x*b1.x + c1.y*b1.y + c1.z*b1.z + c1.w*b1.w
                      + c2.x*b2.x + c2.y*b2.y + c2.z*b2.z + c2.w*b2.w
                      + c3.x*b3.x + c3.y*b3.y + c3.z*b3.z + c3.w*b3.w;
            float wgt = dot * __expf(al - acs[s]);
            float4 x0 = *(const float4*)&Xs[s*16+p0];
            float4 x1 = *(const float4*)&Xs[s*16+p0+4];
            y0.x = fmaf(wgt, x0.x, y0.x); y0.y = fmaf(wgt, x0.y, y0.y);
            y0.z = fmaf(wgt, x0.z, y0.z); y0.w = fmaf(wgt, x0.w, y0.w);
            y1.x = fmaf(wgt, x1.x, y1.x); y1.y = fmaf(wgt, x1.y, y1.y);
            y1.z = fmaf(wgt, x1.z, y1.z); y1.w = fmaf(wgt, x1.w, y1.w);
        }
        float* yo = &g_y[(tokbase+l)*DINNER + h*HEADDIM + p0];
        *(float4*)&yo[0] = y0;
        *(float4*)&yo[4] = y1;
    }
}

// ---------------- inter-chunk scan over 64 chunks ----------------
__global__ void k_scan(const float* __restrict__ ist){
    int b = blockIdx.x>>3, h = blockIdx.x&7;
    int tid = threadIdx.x;                 // (p,n) = tid
    __shared__ float ats[NCHUNK];
    if (tid < NCHUNK)
        ats[tid] = __expf(g_acs[((b*NCHUNK + tid)*NHEADS + h)*CHUNK + CHUNK-1]);
    __syncthreads();
    float S = ist[(h*HEADDIM + (tid>>4))*NSTATE + (tid&15)];
    int idx0 = ((b*NCHUNK)*NHEADS + h)*256 + tid;
    for (int c0=0; c0<NCHUNK; c0+=8){
        float buf[8];
        #pragma unroll
        for (int j=0; j<8; j++) buf[j] = g_stl[idx0 + (c0+j)*(NHEADS*256)];
        #pragma unroll
        for (int j=0; j<8; j++){
            g_prev[idx0 + (c0+j)*(NHEADS*256)] = S;
            S = fmaf(S, ats[c0+j], buf[j]);
        }
    }
}

// ---------------- Y_off + gate + RMSnorm + out_proj + softsign + MLP + residual ----------------
// 32 tokens per block, 1024 threads (warp = token). Weights coalesced -> padded smem.
#define TOKB 32
#define SMEM_OUT_FLOATS (128*65 + 64*65 + 128 + 64 + TOKB*128 + TOKB*64 + TOKB*16 + TOKB*8)
__global__ void __launch_bounds__(1024) k_out(const float* __restrict__ nw,
                                              const float* __restrict__ ow,
                                              const float* __restrict__ mw,
                                              const float* __restrict__ mb){
    extern __shared__ float sm[];
    float* ow_t = sm;                 // [e][d] pitch 65
    float* mw_t = ow_t + 128*65;      // [e][d] pitch 65
    float* nws  = mw_t + 64*65;       // 128
    float* mbs  = nws + 128;          // 64
    float* yrow = mbs + 64;           // [TOKB][128]
    float* trow = yrow + TOKB*128;    // [TOKB][64]
    float* cmr  = trow + TOKB*64;     // [TOKB][16]
    float* ear  = cmr + TOKB*16;      // [TOKB][8]
    int tid = threadIdx.x, w = tid>>5, lane = tid&31;

    // coalesced global read, transposed conflict-free smem write (pitch 65)
    for (int i=tid; i<128*64; i+=1024){ int d=i>>7, e=i&127; ow_t[e*65+d] = ow[i]; }
    for (int i=tid; i<64*64;  i+=1024){ int d=i>>6, e=i&63;  mw_t[e*65+d] = mw[i]; }
    if (tid < 128) nws[tid] = nw[tid];
    if (tid < 64)  mbs[tid] = mb[tid];
    __syncthreads();

    int tok = blockIdx.x*TOKB + w;
    int b = tok >> 13, l = tok & (LL-1);
    int c = l >> 7, lin = l & (CHUNK-1);
    int bc = b*NCHUNK + c;

    if (lane < 16) cmr[w*16+lane] = g_xBC[tok*CONV_DIM + DINNER + NSTATE + lane];
    if (lane < 8)  ear[w*8+lane]  = __expf(g_acs[(bc*NHEADS + lane)*CHUNK + lin]);
    __syncwarp();

    float yv[4]; float ss = 0.f;
    #pragma unroll
    for (int j=0; j<4; j++){
        int ch = lane + 32*j; int h = ch>>4, p = ch&15;
        const float* pv = &g_prev[((bc*NHEADS + h)*HEADDIM + p)*NSTATE];
        float off = 0.f;
        #pragma unroll
        for (int n=0; n<16; n++) off = fmaf(cmr[w*16+n], pv[n], off);
        float y = g_y[tok*DINNER + ch] + ear[w*8+h]*off;
        float z = g_zx[tok*DPROJ + ch];
        y *= z / (1.f + __expf(-z));
        yv[j] = y; ss = fmaf(y, y, ss);
    }
    #pragma unroll
    for (int o=16; o; o>>=1) ss += __shfl_xor_sync(~0u, ss, o);
    float scale = rsqrtf(ss*(1.f/128.f) + 1e-5f);
    #pragma unroll
    for (int j=0; j<4; j++){ int ch = lane + 32*j; yrow[w*128+ch] = yv[j]*scale*nws[ch]; }
    __syncwarp();

    float o1 = 0.f, o2 = 0.f;
    #pragma unroll 8
    for (int e=0; e<128; e++){
        float y2 = yrow[w*128+e];
        o1 = fmaf(y2, ow_t[e*65 + lane],      o1);
        o2 = fmaf(y2, ow_t[e*65 + lane + 32], o2);
    }
    o1 = o1 * rsqrtf(1.f + o1*o1);
    o2 = o2 * rsqrtf(1.f + o2*o2);
    trow[w*64 + lane] = o1; trow[w*64 + lane + 32] = o2;
    __syncwarp();

    float m1 = mbs[lane], m2 = mbs[lane+32];
    #pragma unroll 8
    for (int e=0; e<64; e++){
        float tv = trow[w*64+e];
        m1 = fmaf(tv, mw_t[e*65 + lane],      m1);
        m2 = fmaf(tv, mw_t[e*65 + lane + 32], m2);
    }
    g_h[tok*HH + lane]      += m1;
    g_h[tok*HH + lane + 32] += m2;
}

// ---------------- final: out = h . w_out ----------------
__global__ void k_final(const float* __restrict__ wo, float* __restrict__ out){
    int tid = threadIdx.x;
    int tok = blockIdx.x*8 + (tid>>5); int lane = tid&31;
    float v = g_h[tok*HH + lane]*wo[lane] + g_h[tok*HH + lane + 32]*wo[lane+32];
    #pragma unroll
    for (int o=16; o; o>>=1) v += __shfl_xor_sync(~0u, v, o);
    if (lane == 0) out[tok] = v;
}

extern "C" void kernel_launch(void* const* d_in, const int* in_sizes, int n_in,
                              void* d_out, int out_size){
    const float* x    = (const float*)d_in[0];
    const float* w_in = (const float*)d_in[1];
    const float* w_out= (const float*)d_in[2];
    const float* ipw  = (const float*)d_in[3];
    const float* cw   = (const float*)d_in[4];
    const float* cb   = (const float*)d_in[5];
    const float* dtb  = (const float*)d_in[6];
    const float* alog = (const float*)d_in[7];
    const float* dsk  = (const float*)d_in[8];
    const float* ist  = (const float*)d_in[9];
    const float* nw   = (const float*)d_in[10];
    const float* opw  = (const float*)d_in[11];
    const float* mw   = (const float*)d_in[12];
    const float* mb   = (const float*)d_in[13];
    float* out = (float*)d_out;

    cudaFuncSetAttribute(k_out, cudaFuncAttributeMaxDynamicSharedMemorySize,
                         SMEM_OUT_FLOATS*4);

    k_embed<<<NTOK*HH/256, 256>>>(x, w_in);
    for (int i=0; i<DBLK; i++){
        k_inproj<<<NTOK/16, 320>>>(ipw + (size_t)i*DPROJ*HH);
        k_conv<<<(NTOK/4)*CONV_DIM/256, 256>>>(cw + i*CONV_DIM*DCONV, cb + i*CONV_DIM);
        k_intra<<<BB*NCHUNK*NHEADS, 256>>>(dtb + i*NHEADS, alog + i*NHEADS, dsk + i*NHEADS);
        k_scan<<<BB*NHEADS, 256>>>(ist + (size_t)i*NHEADS*HEADDIM*NSTATE);
        k_out<<<NTOK/TOKB, 1024, SMEM_OUT_FLOATS*4>>>(nw + i*DINNER,
                                                      opw + (size_t)i*HH*DINNER,
                                                      mw + i*HH*HH, mb + i*HH);
    }
    k_final<<<NTOK/8, 256>>>(w_out, out);
}

// round 3
// speedup vs baseline: 1.6147x; 1.1294x over previous
#include <cuda_runtime.h>
#include <math.h>

#define BB 4
#define LL 8192
#define HH 64
#define NSTATE 16
#define DBLK 4
#define DCONV 16
#define DINNER 128
#define HEADDIM 16
#define NHEADS 8
#define CONV_DIM 160
#define DPROJ 296
#define CHUNK 128
#define NCHUNK 64
#define NTOK (BB*LL)

// ---------------- scratch (device globals; no allocation) ----------------
__device__ float g_h[NTOK*HH];
__device__ float g_zx[NTOK*DPROJ];
__device__ float g_xBC[NTOK*CONV_DIM];
__device__ float g_acs[BB*NCHUNK*NHEADS*CHUNK];
__device__ float g_stl[BB*NCHUNK*NHEADS*HEADDIM*NSTATE];
__device__ float g_prev[BB*NCHUNK*NHEADS*HEADDIM*NSTATE];
__device__ float g_y[NTOK*DINNER];

// ---------------- embed ----------------
__global__ void k_embed(const float* __restrict__ x, const float* __restrict__ w_in){
    int i = blockIdx.x*blockDim.x + threadIdx.x;
    int tok = i >> 6; int d = i & 63;
    g_h[i] = x[tok] * w_in[d];
}

// ---------------- in_proj ----------------
__global__ void __launch_bounds__(320) k_inproj(const float* __restrict__ w){
    __shared__ float hs[16*64];
    int tid = threadIdx.x;
    int t0 = blockIdx.x*16;
    for (int i=tid; i<16*64; i+=320) hs[i] = g_h[t0*64 + i];
    __syncthreads();
    if (tid >= DPROJ) return;
    float wr[64];
    #pragma unroll
    for (int d=0; d<64; d++) wr[d] = w[tid*64 + d];
    float acc[16];
    #pragma unroll
    for (int t=0; t<16; t++) acc[t] = 0.f;
    #pragma unroll
    for (int d=0; d<64; d+=4){
        #pragma unroll
        for (int t=0; t<16; t++){
            float4 h4 = *(const float4*)&hs[t*64 + d];
            acc[t] = fmaf(wr[d],   h4.x, acc[t]);
            acc[t] = fmaf(wr[d+1], h4.y, acc[t]);
            acc[t] = fmaf(wr[d+2], h4.z, acc[t]);
            acc[t] = fmaf(wr[d+3], h4.w, acc[t]);
        }
    }
    #pragma unroll
    for (int t=0; t<16; t++) g_zx[(t0+t)*DPROJ + tid] = acc[t];
}

// ---------------- depthwise causal conv + bias + silu ----------------
__global__ void __launch_bounds__(256) k_conv(const float* __restrict__ cw, const float* __restrict__ cb){
    int idx = blockIdx.x*blockDim.x + threadIdx.x;
    int ch  = idx % CONV_DIM;
    int grp = idx / CONV_DIM;
    int tok0 = grp*4;
    int b = tok0 / LL, l0 = tok0 % LL;
    float wv[DCONV];
    #pragma unroll
    for (int k=0; k<DCONV; k++) wv[k] = cw[ch*DCONV + k];
    float in[DCONV+3];
    #pragma unroll
    for (int k=0; k<DCONV+3; k++){
        int ls = l0 - (DCONV-1) + k;
        in[k] = (ls >= 0) ? g_zx[(b*LL + ls)*DPROJ + DINNER + ch] : 0.f;
    }
    float bias = cb[ch];
    #pragma unroll
    for (int j=0; j<4; j++){
        float acc = bias;
        #pragma unroll
        for (int k=0; k<DCONV; k++) acc = fmaf(wv[k], in[j+k], acc);
        g_xBC[(tok0+j)*CONV_DIM + ch] = acc / (1.f + __expf(-acc));
    }
}

// ---------------- intra-chunk: block = (b,c,head-pair), 256 threads ----------------
// thread = (head-half hl, l). Owns full p=16 row: dot computed once per (l,s).
__global__ void __launch_bounds__(256) k_intra(const float* __restrict__ dtb,
                                               const float* __restrict__ alog,
                                               const float* __restrict__ dskip){
    int blk = blockIdx.x;
    int hp = blk & 3;
    int bc = blk >> 2;
    int b = bc / NCHUNK, c = bc % NCHUNK;
    int tid = threadIdx.x;
    int hl = tid >> 7;           // which head of the pair
    int h  = hp*2 + hl;
    int l  = tid & 127;
    int lane = tid & 31;
    __shared__ float Bs[CHUNK*16];
    __shared__ float Cs[CHUNK*16];
    __shared__ float Xs[2][CHUNK*16];
    __shared__ float2 ps[2][CHUNK];      // (cumsum dA, dt)
    __shared__ float dd[2][CHUNK];       // exp(Atot-acs)*dt
    __shared__ float wsum[2][4];
    int tokbase = b*LL + c*CHUNK;

    // dt = softplus(raw + dtb); dA = dt*(-exp(A_log)); warp scan + cross-warp fix
    float vraw = g_zx[(tokbase+l)*DPROJ + DINNER + CONV_DIM + h] + dtb[h];
    float dt = (vraw > 20.f) ? vraw : log1pf(__expf(vraw));
    float sc = dt * (-__expf(alog[h]));
    #pragma unroll
    for (int off=1; off<32; off<<=1){
        float u = __shfl_up_sync(0xffffffffu, sc, off);
        if (lane >= off) sc += u;
    }
    if (lane == 31) wsum[hl][(tid>>5)&3] = sc;
    __syncthreads();
    float pre = 0.f, tot = 0.f;
    int wi = (tid>>5)&3;
    #pragma unroll
    for (int j=0; j<4; j++){
        float wv = wsum[hl][j];
        if (j < wi) pre += wv;
        tot += wv;
    }
    float al = sc + pre;                 // inclusive cumsum for this l
    ps[hl][l] = make_float2(al, dt);
    dd[hl][l] = __expf(tot - al) * dt;
    g_acs[(bc*NHEADS + h)*CHUNK + l] = al;

    // tiles: hl==0 threads load B row l, hl==1 load C row l; each loads own X row
    {
        const float* row = &g_xBC[(tokbase+l)*CONV_DIM];
        if (hl == 0){
            #pragma unroll
            for (int k=0; k<4; k++) *(float4*)&Bs[l*16 + 4*k] = *(const float4*)&row[DINNER + 4*k];
        } else {
            #pragma unroll
            for (int k=0; k<4; k++) *(float4*)&Cs[l*16 + 4*k] = *(const float4*)&row[DINNER + NSTATE + 4*k];
        }
        #pragma unroll
        for (int k=0; k<4; k++) *(float4*)&Xs[hl][l*16 + 4*k] = *(const float4*)&row[h*HEADDIM + 4*k];
    }
    __syncthreads();

    // local chunk states: all 256 threads = (p,n), two passes (one per head)
    {
        int p = tid>>4, n = tid&15;
        #pragma unroll
        for (int hh=0; hh<2; hh++){
            float a0 = 0.f, a1 = 0.f;
            for (int l2=0; l2<CHUNK; l2+=2){
                a0 = fmaf(Bs[l2*16+n]*dd[hh][l2],       Xs[hh][l2*16+p],      a0);
                a1 = fmaf(Bs[(l2+1)*16+n]*dd[hh][l2+1], Xs[hh][(l2+1)*16+p],  a1);
            }
            g_stl[((bc*NHEADS + hp*2+hh)*HEADDIM + p)*NSTATE + n] = a0 + a1;
        }
    }

    // Y_diag (+ skip): thread l owns all 16 p
    {
        float4 c0 = *(const float4*)&Cs[l*16+0];
        float4 c1 = *(const float4*)&Cs[l*16+4];
        float4 c2 = *(const float4*)&Cs[l*16+8];
        float4 c3 = *(const float4*)&Cs[l*16+12];
        float dsk = dskip[h];
        float4 y0 = *(const float4*)&Xs[hl][l*16+0];
        float4 y1 = *(const float4*)&Xs[hl][l*16+4];
        float4 y2 = *(const float4*)&Xs[hl][l*16+8];
        float4 y3 = *(const float4*)&Xs[hl][l*16+12];
        y0.x*=dsk; y0.y*=dsk; y0.z*=dsk; y0.w*=dsk;
        y1.x*=dsk; y1.y*=dsk; y1.z*=dsk; y1.w*=dsk;
        y2.x*=dsk; y2.y*=dsk; y2.z*=dsk; y2.w*=dsk;
        y3.x*=dsk; y3.y*=dsk; y3.z*=dsk; y3.w*=dsk;
        for (int s=0; s<=l; s++){
            float2 pd = ps[hl][s];
            float4 b0 = *(const float4*)&Bs[s*16+0];
            float4 b1 = *(const float4*)&Bs[s*16+4];
            float4 b2 = *(const float4*)&Bs[s*16+8];
            float4 b3 = *(const float4*)&Bs[s*16+12];
            // 4-way tree dot
            float p0 = fmaf(c0.x,b0.x, c0.y*b0.y); p0 = fmaf(c0.z,b0.z,p0); p0 = fmaf(c0.w,b0.w,p0);
            float p1 = fmaf(c1.x,b1.x, c1.y*b1.y); p1 = fmaf(c1.z,b1.z,p1); p1 = fmaf(c1.w,b1.w,p1);
            float p2 = fmaf(c2.x,b2.x, c2.y*b2.y); p2 = fmaf(c2.z,b2.z,p2); p2 = fmaf(c2.w,b2.w,p2);
            float p3 = fmaf(c3.x,b3.x, c3.y*b3.y); p3 = fmaf(c3.z,b3.z,p3); p3 = fmaf(c3.w,b3.w,p3);
            float dot = (p0+p1) + (p2+p3);
            float wgt = dot * (__expf(al - pd.x) * pd.y);
            float4 x0 = *(const float4*)&Xs[hl][s*16+0];
            float4 x1 = *(const float4*)&Xs[hl][s*16+4];
            float4 x2 = *(const float4*)&Xs[hl][s*16+8];
            float4 x3 = *(const float4*)&Xs[hl][s*16+12];
            y0.x = fmaf(wgt,x0.x,y0.x); y0.y = fmaf(wgt,x0.y,y0.y); y0.z = fmaf(wgt,x0.z,y0.z); y0.w = fmaf(wgt,x0.w,y0.w);
            y1.x = fmaf(wgt,x1.x,y1.x); y1.y = fmaf(wgt,x1.y,y1.y); y1.z = fmaf(wgt,x1.z,y1.z); y1.w = fmaf(wgt,x1.w,y1.w);
            y2.x = fmaf(wgt,x2.x,y2.x); y2.y = fmaf(wgt,x2.y,y2.y); y2.z = fmaf(wgt,x2.z,y2.z); y2.w = fmaf(wgt,x2.w,y2.w);
            y3.x = fmaf(wgt,x3.x,y3.x); y3.y = fmaf(wgt,x3.y,y3.y); y3.z = fmaf(wgt,x3.z,y3.z); y3.w = fmaf(wgt,x3.w,y3.w);
        }
        float* yo = &g_y[(tokbase+l)*DINNER + h*HEADDIM];
        *(float4*)&yo[0]  = y0;
        *(float4*)&yo[4]  = y1;
        *(float4*)&yo[8]  = y2;
        *(float4*)&yo[12] = y3;
    }
}

// ---------------- inter-chunk scan ----------------
__global__ void k_scan(const float* __restrict__ ist){
    int b = blockIdx.x>>3, h = blockIdx.x&7;
    int tid = threadIdx.x;
    __shared__ float ats[NCHUNK];
    if (tid < NCHUNK)
        ats[tid] = __expf(g_acs[((b*NCHUNK + tid)*NHEADS + h)*CHUNK + CHUNK-1]);
    __syncthreads();
    float S = ist[(h*HEADDIM + (tid>>4))*NSTATE + (tid&15)];
    int idx0 = ((b*NCHUNK)*NHEADS + h)*256 + tid;
    for (int c0=0; c0<NCHUNK; c0+=8){
        float buf[8];
        #pragma unroll
        for (int j=0; j<8; j++) buf[j] = g_stl[idx0 + (c0+j)*(NHEADS*256)];
        #pragma unroll
        for (int j=0; j<8; j++){
            g_prev[idx0 + (c0+j)*(NHEADS*256)] = S;
            S = fmaf(S, ats[c0+j], buf[j]);
        }
    }
}

// ---------------- Y_off + gate + RMSnorm + out_proj + softsign + MLP + residual ----------------
// 64 tokens/block (half chunk), 1024 threads. thread = (tok, sub16).
#define OTOK 64
#define P1 68
#define SMEM_OUT_FLOATS (128*P1 + 64*P1 + 128 + 64 + 2048 + OTOK*16 + OTOK*8 + OTOK*132 + OTOK*P1)
__global__ void __launch_bounds__(1024) k_out(const float* __restrict__ nw,
                                              const float* __restrict__ ow,
                                              const float* __restrict__ mw,
                                              const float* __restrict__ mb){
    extern __shared__ float sm[];
    float* wT1  = sm;                  // [e][d] pitch P1, 128 rows
    float* wT2  = wT1 + 128*P1;        // [e][d] pitch P1, 64 rows
    float* nws  = wT2 + 64*P1;         // 128
    float* mbs  = nws + 128;           // 64
    float* prevs= mbs + 64;            // 2048 = [h][p][n]
    float* cmr  = prevs + 2048;        // [tok][16]
    float* ear  = cmr + OTOK*16;       // [tok][8]
    float* yn   = ear + OTOK*8;        // [tok][128] pitch 132
    float* trow = yn + OTOK*132;       // [tok][64] pitch P1... pitch 68
    int tid = threadIdx.x;
    int tok = tid >> 4, sub = tid & 15;
    int tok0 = blockIdx.x*OTOK;
    int bc = tok0 >> 7;                 // global chunk index b*NCHUNK+c

    for (int i=tid; i<128*64; i+=1024){ int d=i>>7, e=i&127; wT1[e*P1+d] = ow[i]; }
    for (int i=tid; i<64*64;  i+=1024){ int d=i>>6, e=i&63;  wT2[e*P1+d] = mw[i]; }
    for (int i=tid; i<2048;   i+=1024) prevs[i] = g_prev[bc*2048 + i];
    if (tid < 128) nws[tid] = nw[tid];
    if (tid < 64)  mbs[tid] = mb[tid];
    { int t=tid>>4, n=tid&15; cmr[tid] = g_xBC[(tok0+t)*CONV_DIM + DINNER + NSTATE + n]; }
    if (tid < OTOK*8){
        int t=tid>>3, h=tid&7;
        ear[tid] = __expf(g_acs[(bc*NHEADS+h)*CHUNK + ((tok0+t)&(CHUNK-1))]);
    }
    __syncthreads();

    int gtok = tok0 + tok;
    float4 cm0 = *(const float4*)&cmr[tok*16+0];
    float4 cm1 = *(const float4*)&cmr[tok*16+4];
    float4 cm2 = *(const float4*)&cmr[tok*16+8];
    float4 cm3 = *(const float4*)&cmr[tok*16+12];

    float4 ya = *(const float4*)&g_y[gtok*DINNER + sub*8];
    float4 yb = *(const float4*)&g_y[gtok*DINNER + sub*8 + 4];
    float4 za = *(const float4*)&g_zx[gtok*DPROJ + sub*8];
    float4 zb = *(const float4*)&g_zx[gtok*DPROJ + sub*8 + 4];
    float yin[8] = {ya.x,ya.y,ya.z,ya.w,yb.x,yb.y,yb.z,yb.w};
    float zin[8] = {za.x,za.y,za.z,za.w,zb.x,zb.y,zb.z,zb.w};

    float out8[8]; float ss = 0.f;
    #pragma unroll
    for (int j=0; j<8; j++){
        int ch = sub*8 + j; int h = ch>>4, p = ch&15;
        const float4* pv = (const float4*)&prevs[h*256 + p*16];
        float4 v0 = pv[0], v1 = pv[1], v2 = pv[2], v3 = pv[3];
        float q0 = fmaf(cm0.x,v0.x, cm0.y*v0.y); q0 = fmaf(cm0.z,v0.z,q0); q0 = fmaf(cm0.w,v0.w,q0);
        float q1 = fmaf(cm1.x,v1.x, cm1.y*v1.y); q1 = fmaf(cm1.z,v1.z,q1); q1 = fmaf(cm1.w,v1.w,q1);
        float q2 = fmaf(cm2.x,v2.x, cm2.y*v2.y); q2 = fmaf(cm2.z,v2.z,q2); q2 = fmaf(cm2.w,v2.w,q2);
        float q3 = fmaf(cm3.x,v3.x, cm3.y*v3.y); q3 = fmaf(cm3.z,v3.z,q3); q3 = fmaf(cm3.w,v3.w,q3);
        float off = (q0+q1) + (q2+q3);
        float y = yin[j] + ear[tok*8+h]*off;
        float z = zin[j];
        y *= z / (1.f + __expf(-z));
        out8[j] = y; ss = fmaf(y, y, ss);
    }
    #pragma unroll
    for (int o=8; o; o>>=1) ss += __shfl_xor_sync(0xffffffffu, ss, o, 16);
    float scale = rsqrtf(ss*(1.f/128.f) + 1e-5f);
    {
        float4 n0 = *(const float4*)&nws[sub*8];
        float4 n1 = *(const float4*)&nws[sub*8+4];
        float4 w0, w1;
        w0.x = out8[0]*scale*n0.x; w0.y = out8[1]*scale*n0.y;
        w0.z = out8[2]*scale*n0.z; w0.w = out8[3]*scale*n0.w;
        w1.x = out8[4]*scale*n1.x; w1.y = out8[5]*scale*n1.y;
        w1.z = out8[6]*scale*n1.z; w1.w = out8[7]*scale*n1.w;
        *(float4*)&yn[tok*132 + sub*8]     = w0;
        *(float4*)&yn[tok*132 + sub*8 + 4] = w1;
    }
    __syncthreads();

    // GEMM1: o[tok][4d] = sum_e yn[tok][e] * W1[d][e]
    float4 a = make_float4(0.f,0.f,0.f,0.f);
    #pragma unroll 8
    for (int e=0; e<128; e++){
        float yv = yn[tok*132 + e];
        float4 w4 = *(const float4*)&wT1[e*P1 + sub*4];
        a.x = fmaf(yv, w4.x, a.x); a.y = fmaf(yv, w4.y, a.y);
        a.z = fmaf(yv, w4.z, a.z); a.w = fmaf(yv, w4.w, a.w);
    }
    a.x *= rsqrtf(1.f + a.x*a.x); a.y *= rsqrtf(1.f + a.y*a.y);
    a.z *= rsqrtf(1.f + a.z*a.z); a.w *= rsqrtf(1.f + a.w*a.w);
    *(float4*)&trow[tok*P1 + sub*4] = a;
    __syncthreads();

    // GEMM2: m[tok][4d] = mb + sum_e t[tok][e] * W2[d][e]
    float4 m = *(const float4*)&mbs[sub*4];
    #pragma unroll 8
    for (int e=0; e<64; e++){
        float tv = trow[tok*P1 + e];
        float4 w4 = *(const float4*)&wT2[e*P1 + sub*4];
        m.x = fmaf(tv, w4.x, m.x); m.y = fmaf(tv, w4.y, m.y);
        m.z = fmaf(tv, w4.z, m.z); m.w = fmaf(tv, w4.w, m.w);
    }
    float4 hv = *(const float4*)&g_h[gtok*HH + sub*4];
    hv.x += m.x; hv.y += m.y; hv.z += m.z; hv.w += m.w;
    *(float4*)&g_h[gtok*HH + sub*4] = hv;
}

// ---------------- final ----------------
__global__ void k_final(const float* __restrict__ wo, float* __restrict__ out){
    int tid = threadIdx.x;
    int tok = blockIdx.x*8 + (tid>>5); int lane = tid&31;
    float v = g_h[tok*HH + lane]*wo[lane] + g_h[tok*HH + lane + 32]*wo[lane+32];
    #pragma unroll
    for (int o=16; o; o>>=1) v += __shfl_xor_sync(~0u, v, o);
    if (lane == 0) out[tok] = v;
}

extern "C" void kernel_launch(void* const* d_in, const int* in_sizes, int n_in,
                              void* d_out, int out_size){
    const float* x    = (const float*)d_in[0];
    const float* w_in = (const float*)d_in[1];
    const float* w_out= (const float*)d_in[2];
    const float* ipw  = (const float*)d_in[3];
    const float* cw   = (const float*)d_in[4];
    const float* cb   = (const float*)d_in[5];
    const float* dtb  = (const float*)d_in[6];
    const float* alog = (const float*)d_in[7];
    const float* dsk  = (const float*)d_in[8];
    const float* ist  = (const float*)d_in[9];
    const float* nw   = (const float*)d_in[10];
    const float* opw  = (const float*)d_in[11];
    const float* mw   = (const float*)d_in[12];
    const float* mb   = (const float*)d_in[13];
    float* out = (float*)d_out;

    cudaFuncSetAttribute(k_out, cudaFuncAttributeMaxDynamicSharedMemorySize,
                         SMEM_OUT_FLOATS*4);

    k_embed<<<NTOK*HH/256, 256>>>(x, w_in);
    for (int i=0; i<DBLK; i++){
        k_inproj<<<NTOK/16, 320>>>(ipw + (size_t)i*DPROJ*HH);
        k_conv<<<(NTOK/4)*CONV_DIM/256, 256>>>(cw + i*CONV_DIM*DCONV, cb + i*CONV_DIM);
        k_intra<<<BB*NCHUNK*4, 256>>>(dtb + i*NHEADS, alog + i*NHEADS, dsk + i*NHEADS);
        k_scan<<<BB*NHEADS, 256>>>(ist + (size_t)i*NHEADS*HEADDIM*NSTATE);
        k_out<<<NTOK/OTOK, 1024, SMEM_OUT_FLOATS*4>>>(nw + i*DINNER,
                                                      opw + (size_t)i*HH*DINNER,
                                                      mw + i*HH*HH, mb + i*HH);
    }
    k_final<<<NTOK/8, 256>>>(w_out, out);
}

// round 5
// speedup vs baseline: 1.9804x; 1.2265x over previous
#include <cuda_runtime.h>
#include <math.h>

#define BB 4
#define LL 8192
#define HH 64
#define NSTATE 16
#define DBLK 4
#define DCONV 16
#define DINNER 128
#define HEADDIM 16
#define NHEADS 8
#define CONV_DIM 160
#define DPROJ 296
#define QSUB 32
#define NSUB (LL/QSUB)
#define NTOK (BB*LL)

// ---------------- scratch (device globals; no allocation) ----------------
__device__ float g_h[NTOK*HH];
__device__ float g_zx[NTOK*DPROJ];
__device__ float g_xBC[NTOK*CONV_DIM];
__device__ float g_acs[BB*NSUB*NHEADS*QSUB];          // within-subchunk cumsum of dA
__device__ float g_stl[BB*NSUB*NHEADS*256];           // local subchunk states [n][p]
__device__ float g_prev[BB*NSUB*NHEADS*256];          // scanned prev states [n][p]
__device__ float g_y[NTOK*DINNER];

// ---------------- embed ----------------
__global__ void k_embed(const float* __restrict__ x, const float* __restrict__ w_in){
    int i = blockIdx.x*blockDim.x + threadIdx.x;
    int tok = i >> 6; int d = i & 63;
    g_h[i] = x[tok] * w_in[d];
}

// ---------------- in_proj ----------------
__global__ void __launch_bounds__(320) k_inproj(const float* __restrict__ w){
    __shared__ float hs[16*64];
    int tid = threadIdx.x;
    int t0 = blockIdx.x*16;
    for (int i=tid; i<16*64; i+=320) hs[i] = g_h[t0*64 + i];
    __syncthreads();
    if (tid >= DPROJ) return;
    float acc[16];
    #pragma unroll
    for (int t=0; t<16; t++) acc[t] = 0.f;
    #pragma unroll
    for (int half=0; half<2; half++){
        float wr[32];
        #pragma unroll
        for (int d=0; d<32; d++) wr[d] = w[tid*64 + half*32 + d];
        #pragma unroll
        for (int d=0; d<32; d+=4){
            #pragma unroll
            for (int t=0; t<16; t++){
                float4 h4 = *(const float4*)&hs[t*64 + half*32 + d];
                acc[t] = fmaf(wr[d],   h4.x, acc[t]);
                acc[t] = fmaf(wr[d+1], h4.y, acc[t]);
                acc[t] = fmaf(wr[d+2], h4.z, acc[t]);
                acc[t] = fmaf(wr[d+3], h4.w, acc[t]);
            }
        }
    }
    #pragma unroll
    for (int t=0; t<16; t++) g_zx[(t0+t)*DPROJ + tid] = acc[t];
}

// ---------------- depthwise causal conv + bias + silu ----------------
__global__ void __launch_bounds__(256) k_conv(const float* __restrict__ cw, const float* __restrict__ cb){
    int idx = blockIdx.x*blockDim.x + threadIdx.x;
    int ch  = idx % CONV_DIM;
    int grp = idx / CONV_DIM;
    int tok0 = grp*4;
    int b = tok0 / LL, l0 = tok0 % LL;
    float wv[DCONV];
    #pragma unroll
    for (int k=0; k<DCONV; k++) wv[k] = cw[ch*DCONV + k];
    float in[DCONV+3];
    #pragma unroll
    for (int k=0; k<DCONV+3; k++){
        int ls = l0 - (DCONV-1) + k;
        in[k] = (ls >= 0) ? g_zx[(b*LL + ls)*DPROJ + DINNER + ch] : 0.f;
    }
    float bias = cb[ch];
    #pragma unroll
    for (int j=0; j<4; j++){
        float acc = bias;
        #pragma unroll
        for (int k=0; k<DCONV; k++) acc = fmaf(wv[k], in[j+k], acc);
        g_xBC[(tok0+j)*CONV_DIM + ch] = acc / (1.f + __expf(-acc));
    }
}

// ---------------- intra-subchunk (Q=32): block = (b, 128-token group, head-pair) ----------------
__global__ void __launch_bounds__(256) k_intra(const float* __restrict__ dtb,
                                               const float* __restrict__ alog,
                                               const float* __restrict__ dskip){
    int blk = blockIdx.x;
    int hp = blk & 3;
    int grp = blk >> 2;                 // 0..BB*64-1
    int b = grp >> 6, g = grp & 63;
    int tokbase = b*LL + g*128;
    int tid = threadIdx.x;
    int hl = tid >> 7;                  // head of the pair
    int l  = tid & 127;                 // token in group; warp == one subchunk
    int lane = tid & 31;
    int h = hp*2 + hl;
    __shared__ float Bs[128*16];
    __shared__ float Cs[128*16];
    __shared__ float Xs[2][128*16];
    __shared__ float2 ps[2][128];       // (within-sub cumsum dA, dt)
    __shared__ float dd[2][128];        // exp(subTot - acs)*dt

    // dt = softplus(raw + dtb); within-subchunk warp scan of dA
    float vraw = g_zx[(tokbase+l)*DPROJ + DINNER + CONV_DIM + h] + dtb[h];
    float dt = (vraw > 20.f) ? vraw : log1pf(__expf(vraw));
    float sc = dt * (-__expf(alog[h]));
    #pragma unroll
    for (int off=1; off<32; off<<=1){
        float u = __shfl_up_sync(0xffffffffu, sc, off);
        if (lane >= off) sc += u;
    }
    float tot = __shfl_sync(0xffffffffu, sc, 31);
    ps[hl][l] = make_float2(sc, dt);
    dd[hl][l] = __expf(tot - sc) * dt;
    int gsub = b*NSUB + g*4 + (l>>5);
    g_acs[(gsub*NHEADS + h)*QSUB + lane] = sc;

    // tiles
    {
        const float* row = &g_xBC[(tokbase+l)*CONV_DIM];
        if (hl == 0){
            #pragma unroll
            for (int k=0;k<4;k++) *(float4*)&Bs[l*16+4*k] = *(const float4*)&row[DINNER+4*k];
        } else {
            #pragma unroll
            for (int k=0;k<4;k++) *(float4*)&Cs[l*16+4*k] = *(const float4*)&row[DINNER+NSTATE+4*k];
        }
        #pragma unroll
        for (int k=0;k<4;k++) *(float4*)&Xs[hl][l*16+4*k] = *(const float4*)&row[h*HEADDIM+4*k];
    }
    __syncthreads();

    // local subchunk states, layout [n][p]: thread = (hh, q, n, ph)
    {
        int hh = tid>>7, q=(tid>>5)&3, n=(tid>>1)&15, ph=tid&1;
        float a0=0,a1=0,a2=0,a3=0,a4=0,a5=0,a6=0,a7=0;
        int l0 = q*32;
        #pragma unroll 4
        for (int ll=0; ll<32; ll++){
            int lr = l0+ll;
            float bd = Bs[lr*16+n]*dd[hh][lr];
            float4 xa = *(const float4*)&Xs[hh][lr*16+ph*8];
            float4 xb = *(const float4*)&Xs[hh][lr*16+ph*8+4];
            a0=fmaf(bd,xa.x,a0); a1=fmaf(bd,xa.y,a1); a2=fmaf(bd,xa.z,a2); a3=fmaf(bd,xa.w,a3);
            a4=fmaf(bd,xb.x,a4); a5=fmaf(bd,xb.y,a5); a6=fmaf(bd,xb.z,a6); a7=fmaf(bd,xb.w,a7);
        }
        int base = ((b*NSUB + g*4 + q)*NHEADS + hp*2+hh)*256 + n*16 + ph*8;
        *(float4*)&g_stl[base]   = make_float4(a0,a1,a2,a3);
        *(float4*)&g_stl[base+4] = make_float4(a4,a5,a6,a7);
    }

    // Y_diag (+ skip) within subchunk: thread (hl, l)
    {
        float4 c0 = *(const float4*)&Cs[l*16+0];
        float4 c1 = *(const float4*)&Cs[l*16+4];
        float4 c2 = *(const float4*)&Cs[l*16+8];
        float4 c3 = *(const float4*)&Cs[l*16+12];
        float al = sc;
        float dsk = dskip[h];
        float4 y0 = *(const float4*)&Xs[hl][l*16+0];
        float4 y1 = *(const float4*)&Xs[hl][l*16+4];
        float4 y2 = *(const float4*)&Xs[hl][l*16+8];
        float4 y3 = *(const float4*)&Xs[hl][l*16+12];
        y0.x*=dsk; y0.y*=dsk; y0.z*=dsk; y0.w*=dsk;
        y1.x*=dsk; y1.y*=dsk; y1.z*=dsk; y1.w*=dsk;
        y2.x*=dsk; y2.y*=dsk; y2.z*=dsk; y2.w*=dsk;
        y3.x*=dsk; y3.y*=dsk; y3.z*=dsk; y3.w*=dsk;
        int s0 = l & ~31;
        for (int s=s0; s<=l; s++){
            float2 pd = ps[hl][s];
            float4 b0 = *(const float4*)&Bs[s*16+0];
            float4 b1 = *(const float4*)&Bs[s*16+4];
            float4 b2 = *(const float4*)&Bs[s*16+8];
            float4 b3 = *(const float4*)&Bs[s*16+12];
            float p0 = fmaf(c0.x,b0.x, c0.y*b0.y); p0 = fmaf(c0.z,b0.z,p0); p0 = fmaf(c0.w,b0.w,p0);
            float p1 = fmaf(c1.x,b1.x, c1.y*b1.y); p1 = fmaf(c1.z,b1.z,p1); p1 = fmaf(c1.w,b1.w,p1);
            float p2 = fmaf(c2.x,b2.x, c2.y*b2.y); p2 = fmaf(c2.z,b2.z,p2); p2 = fmaf(c2.w,b2.w,p2);
            float p3 = fmaf(c3.x,b3.x, c3.y*b3.y); p3 = fmaf(c3.z,b3.z,p3); p3 = fmaf(c3.w,b3.w,p3);
            float dot = (p0+p1) + (p2+p3);
            float wgt = dot * (__expf(al - pd.x) * pd.y);
            float4 x0 = *(const float4*)&Xs[hl][s*16+0];
            float4 x1 = *(const float4*)&Xs[hl][s*16+4];
            float4 x2 = *(const float4*)&Xs[hl][s*16+8];
            float4 x3 = *(const float4*)&Xs[hl][s*16+12];
            y0.x = fmaf(wgt,x0.x,y0.x); y0.y = fmaf(wgt,x0.y,y0.y); y0.z = fmaf(wgt,x0.z,y0.z); y0.w = fmaf(wgt,x0.w,y0.w);
            y1.x = fmaf(wgt,x1.x,y1.x); y1.y = fmaf(wgt,x1.y,y1.y); y1.z = fmaf(wgt,x1.z,y1.z); y1.w = fmaf(wgt,x1.w,y1.w);
            y2.x = fmaf(wgt,x2.x,y2.x); y2.y = fmaf(wgt,x2.y,y2.y); y2.z = fmaf(wgt,x2.z,y2.z); y2.w = fmaf(wgt,x2.w,y2.w);
            y3.x = fmaf(wgt,x3.x,y3.x); y3.y = fmaf(wgt,x3.y,y3.y); y3.z = fmaf(wgt,x3.z,y3.z); y3.w = fmaf(wgt,x3.w,y3.w);
        }
        float* yo = &g_y[(tokbase+l)*DINNER + h*HEADDIM];
        *(float4*)&yo[0]  = y0;
        *(float4*)&yo[4]  = y1;
        *(float4*)&yo[8]  = y2;
        *(float4*)&yo[12] = y3;
    }
}

// ---------------- inter-subchunk scan (256 subchunks per (b,h)) ----------------
__global__ void k_scan(const float* __restrict__ ist){
    int b = blockIdx.x>>3, h = blockIdx.x&7;
    int tid = threadIdx.x;
    __shared__ float ats[NSUB];
    ats[tid] = __expf(g_acs[((b*NSUB + tid)*NHEADS + h)*QSUB + QSUB-1]);
    __syncthreads();
    // element id = n*16+p ; ist layout [h][p][n]
    float S = ist[h*256 + (tid&15)*16 + (tid>>4)];
    size_t idx0 = ((size_t)(b*NSUB)*NHEADS + h)*256 + tid;
    const size_t stride = (size_t)NHEADS*256;
    for (int c0=0; c0<NSUB; c0+=8){
        float buf[8];
        #pragma unroll
        for (int j=0; j<8; j++) buf[j] = g_stl[idx0 + (size_t)(c0+j)*stride];
        #pragma unroll
        for (int j=0; j<8; j++){
            g_prev[idx0 + (size_t)(c0+j)*stride] = S;
            S = fmaf(S, ats[c0+j], buf[j]);
        }
    }
}

// ---------------- Y_off + gate + RMSnorm + out_proj + softsign + MLP + residual ----------------
// 64 tokens/block, 256 threads. Register-tiled 4x4 GEMMs over transposed smem.
#define KP 68
#define SMEM_OUT_FLOATS (128*KP + 64*KP + 128*KP + 64*KP + 16*260 + 64*16 + 64*8 + 128 + 64)
__global__ void __launch_bounds__(256) k_out(const float* __restrict__ nw,
                                             const float* __restrict__ ow,
                                             const float* __restrict__ mw,
                                             const float* __restrict__ mb){
    extern __shared__ float sm[];
    float* wT1  = sm;                  // [e=128][d=64] pitch KP
    float* wT2  = wT1 + 128*KP;        // [e=64][d=64] pitch KP
    float* ynT  = wT2 + 64*KP;         // [e=128][tok=64] pitch KP
    float* tT   = ynT + 128*KP;        // [e=64][tok=64] pitch KP
    float* prevs= tT + 64*KP;          // [2 sub][8 h] pitch 260, element n*16+p
    float* cmr  = prevs + 16*260;      // [64 tok][16]
    float* ear  = cmr + 64*16;         // [64 tok][8]
    float* nws  = ear + 64*8;          // 128
    float* mbs  = nws + 128;           // 64
    int tid = threadIdx.x;
    int tok0 = blockIdx.x*64;
    int b = tok0 >> 13;
    int lbase = tok0 & (LL-1);
    int sub0 = b*NSUB + (lbase>>5);

    for (int i=tid; i<128*64; i+=256){ int d=i>>7, e=i&127; wT1[e*KP+d] = ow[i]; }
    for (int i=tid; i<64*64;  i+=256){ int d=i>>6, e=i&63;  wT2[e*KP+d] = mw[i]; }
    for (int i=tid; i<4096; i+=256){
        int sl=i>>11, r=i&2047, hh=r>>8, el=r&255;
        prevs[(sl*8+hh)*260+el] = g_prev[((size_t)(sub0+sl)*NHEADS+hh)*256 + el];
    }
    for (int i=tid; i<1024; i+=256){ int t=i>>4, n=i&15;
        cmr[i] = g_xBC[(tok0+t)*CONV_DIM + DINNER + NSTATE + n]; }
    for (int i=tid; i<512; i+=256){ int t=i>>3, hh=i&7;
        ear[i] = __expf(g_acs[((sub0 + (t>>5))*NHEADS + hh)*QSUB + (t&31)]); }
    if (tid < 128) nws[tid] = nw[tid];
    if (tid < 64)  mbs[tid] = mb[tid];
    __syncthreads();

    // Y_off + gate + RMS: thread = (tok = tid>>2, q = tid&3) owns 32 channels
    {
        int tok = tid>>2, q = tid&3;
        int sl = tok>>5;
        int gtok = tok0 + tok;
        float cm[16];
        #pragma unroll
        for (int n=0; n<16; n++) cm[n] = cmr[tok*16+n];
        float yv[32]; float ss = 0.f;
        #pragma unroll
        for (int hh2=0; hh2<2; hh2++){
            int h = q*2 + hh2;
            const float* pv = &prevs[(sl*8+h)*260];
            float e_a = ear[tok*8+h];
            #pragma unroll
            for (int p4=0; p4<4; p4++){
                float4 acc = make_float4(0.f,0.f,0.f,0.f);
                #pragma unroll
                for (int n=0; n<16; n++){
                    float4 pvv = *(const float4*)&pv[n*16 + p4*4];
                    acc.x = fmaf(cm[n], pvv.x, acc.x);
                    acc.y = fmaf(cm[n], pvv.y, acc.y);
                    acc.z = fmaf(cm[n], pvv.z, acc.z);
                    acc.w = fmaf(cm[n], pvv.w, acc.w);
                }
                int ch = h*16 + p4*4;
                float4 yi = *(const float4*)&g_y[(size_t)gtok*DINNER + ch];
                float4 zi = *(const float4*)&g_zx[(size_t)gtok*DPROJ + ch];
                float y0 = yi.x + e_a*acc.x, z0 = zi.x; y0 *= z0/(1.f+__expf(-z0));
                float y1 = yi.y + e_a*acc.y, z1 = zi.y; y1 *= z1/(1.f+__expf(-z1));
                float y2 = yi.z + e_a*acc.z, z2 = zi.z; y2 *= z2/(1.f+__expf(-z2));
                float y3 = yi.w + e_a*acc.w, z3 = zi.w; y3 *= z3/(1.f+__expf(-z3));
                int jb = hh2*16 + p4*4;
                yv[jb]=y0; yv[jb+1]=y1; yv[jb+2]=y2; yv[jb+3]=y3;
                ss = fmaf(y0,y0, fmaf(y1,y1, fmaf(y2,y2, fmaf(y3,y3, ss))));
            }
        }
        ss += __shfl_xor_sync(0xffffffffu, ss, 1);
        ss += __shfl_xor_sync(0xffffffffu, ss, 2);
        float scale = rsqrtf(ss*(1.f/128.f) + 1e-5f);
        #pragma unroll
        for (int j=0; j<32; j++){
            int ch = q*32 + j;
            ynT[ch*KP + tok] = yv[j]*scale*nws[ch];
        }
    }
    __syncthreads();

    // GEMM1 (out_proj) + softsign: thread (i = tid>>4 tok-quad, j = tid&15 d-quad)
    {
        int i = tid>>4, j = tid&15;
        float a00=0,a01=0,a02=0,a03=0, a10=0,a11=0,a12=0,a13=0;
        float a20=0,a21=0,a22=0,a23=0, a30=0,a31=0,a32=0,a33=0;
        #pragma unroll 8
        for (int e=0; e<128; e++){
            float4 yv4 = *(const float4*)&ynT[e*KP + i*4];
            float4 wv4 = *(const float4*)&wT1[e*KP + j*4];
            a00=fmaf(yv4.x,wv4.x,a00); a01=fmaf(yv4.x,wv4.y,a01); a02=fmaf(yv4.x,wv4.z,a02); a03=fmaf(yv4.x,wv4.w,a03);
            a10=fmaf(yv4.y,wv4.x,a10); a11=fmaf(yv4.y,wv4.y,a11); a12=fmaf(yv4.y,wv4.z,a12); a13=fmaf(yv4.y,wv4.w,a13);
            a20=fmaf(yv4.z,wv4.x,a20); a21=fmaf(yv4.z,wv4.y,a21); a22=fmaf(yv4.z,wv4.z,a22); a23=fmaf(yv4.z,wv4.w,a23);
            a30=fmaf(yv4.w,wv4.x,a30); a31=fmaf(yv4.w,wv4.y,a31); a32=fmaf(yv4.w,wv4.z,a32); a33=fmaf(yv4.w,wv4.w,a33);
        }
        #define SS(v) ((v)*rsqrtf(1.f+(v)*(v)))
        tT[(j*4+0)*KP + i*4+0]=SS(a00); tT[(j*4+1)*KP + i*4+0]=SS(a01); tT[(j*4+2)*KP + i*4+0]=SS(a02); tT[(j*4+3)*KP + i*4+0]=SS(a03);
        tT[(j*4+0)*KP + i*4+1]=SS(a10); tT[(j*4+1)*KP + i*4+1]=SS(a11); tT[(j*4+2)*KP + i*4+1]=SS(a12); tT[(j*4+3)*KP + i*4+1]=SS(a13);
        tT[(j*4+0)*KP + i*4+2]=SS(a20); tT[(j*4+1)*KP + i*4+2]=SS(a21); tT[(j*4+2)*KP + i*4+2]=SS(a22); tT[(j*4+3)*KP + i*4+2]=SS(a23);
        tT[(j*4+0)*KP + i*4+3]=SS(a30); tT[(j*4+1)*KP + i*4+3]=SS(a31); tT[(j*4+2)*KP + i*4+3]=SS(a32); tT[(j*4+3)*KP + i*4+3]=SS(a33);
        #undef SS
    }
    __syncthreads();

    // GEMM2 (MLP) + residual
    {
        int i = tid>>4, j = tid&15;
        float4 mbv = *(const float4*)&mbs[j*4];
        float a00=mbv.x,a01=mbv.y,a02=mbv.z,a03=mbv.w;
        float a10=mbv.x,a11=mbv.y,a12=mbv.z,a13=mbv.w;
        float a20=mbv.x,a21=mbv.y,a22=mbv.z,a23=mbv.w;
        float a30=mbv.x,a31=mbv.y,a32=mbv.z,a33=mbv.w;
        #pragma unroll 8
        for (int e=0; e<64; e++){
            float4 tv4 = *(const float4*)&tT[e*KP + i*4];
            float4 wv4 = *(const float4*)&wT2[e*KP + j*4];
            a00=fmaf(tv4.x,wv4.x,a00); a01=fmaf(tv4.x,wv4.y,a01); a02=fmaf(tv4.x,wv4.z,a02); a03=fmaf(tv4.x,wv4.w,a03);
            a10=fmaf(tv4.y,wv4.x,a10); a11=fmaf(tv4.y,wv4.y,a11); a12=fmaf(tv4.y,wv4.z,a12); a13=fmaf(tv4.y,wv4.w,a13);
            a20=fmaf(tv4.z,wv4.x,a20); a21=fmaf(tv4.z,wv4.y,a21); a22=fmaf(tv4.z,wv4.z,a22); a23=fmaf(tv4.z,wv4.w,a23);
            a30=fmaf(tv4.w,wv4.x,a30); a31=fmaf(tv4.w,wv4.y,a31); a32=fmaf(tv4.w,wv4.z,a32); a33=fmaf(tv4.w,wv4.w,a33);
        }
        int gt0 = tok0 + i*4;
        float4 h0 = *(const float4*)&g_h[(size_t)(gt0+0)*HH + j*4];
        float4 h1 = *(const float4*)&g_h[(size_t)(gt0+1)*HH + j*4];
        float4 h2 = *(const float4*)&g_h[(size_t)(gt0+2)*HH + j*4];
        float4 h3 = *(const float4*)&g_h[(size_t)(gt0+3)*HH + j*4];
        h0.x+=a00; h0.y+=a01; h0.z+=a02; h0.w+=a03;
        h1.x+=a10; h1.y+=a11; h1.z+=a12; h1.w+=a13;
        h2.x+=a20; h2.y+=a21; h2.z+=a22; h2.w+=a23;
        h3.x+=a30; h3.y+=a31; h3.z+=a32; h3.w+=a33;
        *(float4*)&g_h[(size_t)(gt0+0)*HH + j*4] = h0;
        *(float4*)&g_h[(size_t)(gt0+1)*HH + j*4] = h1;
        *(float4*)&g_h[(size_t)(gt0+2)*HH + j*4] = h2;
        *(float4*)&g_h[(size_t)(gt0+3)*HH + j*4] = h3;
    }
}

// ---------------- final ----------------
__global__ void k_final(const float* __restrict__ wo, float* __restrict__ out){
    int tid = threadIdx.x;
    int tok = blockIdx.x*8 + (tid>>5); int lane = tid&31;
    float v = g_h[tok*HH + lane]*wo[lane] + g_h[tok*HH + lane + 32]*wo[lane+32];
    #pragma unroll
    for (int o=16; o; o>>=1) v += __shfl_xor_sync(~0u, v, o);
    if (lane == 0) out[tok] = v;
}

extern "C" void kernel_launch(void* const* d_in, const int* in_sizes, int n_in,
                              void* d_out, int out_size){
    const float* x    = (const float*)d_in[0];
    const float* w_in = (const float*)d_in[1];
    const float* w_out= (const float*)d_in[2];
    const float* ipw  = (const float*)d_in[3];
    const float* cw   = (const float*)d_in[4];
    const float* cb   = (const float*)d_in[5];
    const float* dtb  = (const float*)d_in[6];
    const float* alog = (const float*)d_in[7];
    const float* dsk  = (const float*)d_in[8];
    const float* ist  = (const float*)d_in[9];
    const float* nw   = (const float*)d_in[10];
    const float* opw  = (const float*)d_in[11];
    const float* mw   = (const float*)d_in[12];
    const float* mb   = (const float*)d_in[13];
    float* out = (float*)d_out;

    cudaFuncSetAttribute(k_out, cudaFuncAttributeMaxDynamicSharedMemorySize,
                         SMEM_OUT_FLOATS*4);

    k_embed<<<NTOK*HH/256, 256>>>(x, w_in);
    for (int i=0; i<DBLK; i++){
        k_inproj<<<NTOK/16, 320>>>(ipw + (size_t)i*DPROJ*HH);
        k_conv<<<(NTOK/4)*CONV_DIM/256, 256>>>(cw + i*CONV_DIM*DCONV, cb + i*CONV_DIM);
        k_intra<<<BB*64*4, 256>>>(dtb + i*NHEADS, alog + i*NHEADS, dsk + i*NHEADS);
        k_scan<<<BB*NHEADS, 256>>>(ist + (size_t)i*NHEADS*HEADDIM*NSTATE);
        k_out<<<NTOK/64, 256, SMEM_OUT_FLOATS*4>>>(nw + i*DINNER,
                                                   opw + (size_t)i*HH*DINNER,
                                                   mw + i*HH*HH, mb + i*HH);
    }
    k_final<<<NTOK/8, 256>>>(w_out, out);
}